// round 1
// baseline (speedup 1.0000x reference)
#include <cuda_runtime.h>
#include <math.h>

// Problem constants
#define BB 64      // batch
#define TT 512     // seq len
#define DD 512     // input size
#define HH 1024    // hidden size
#define GG 4096    // 4*H

// Scratch: xz[dir][t][b][4H]  (2*512*64*4096 floats = 1 GiB)
__device__ float g_xz[(size_t)2 * TT * BB * GG];
// h double-buffered by step parity: g_h[parity][dir*B*H + b*H + j]
__device__ float g_h[2][2 * BB * HH];
// cell state: g_c[dir*B*H + b*H + j]
__device__ float g_c[2 * BB * HH];

// ---------------------------------------------------------------------------
// Zero-init h (parity 0) and c
// ---------------------------------------------------------------------------
__global__ void init_kernel() {
    int i = blockIdx.x * blockDim.x + threadIdx.x;
    const int N = 2 * BB * HH;
    if (i < N) {
        g_h[0][i] = 0.0f;
        g_c[i] = 0.0f;
    }
}

// ---------------------------------------------------------------------------
// Input projection: xz[dir][t][b][g] = sum_d X[b][t][d] * Wx[dir][d][g] + bias
// Classic 128x128x8 fp32 SGEMM, 256 threads, 8x8 per thread.
// M = B*T = 32768 (m = b*T + t), K = 512, N = 4096. All dims divide tiles.
// ---------------------------------------------------------------------------
__global__ void proj_kernel(const float* __restrict__ X,
                            const float* __restrict__ Wxf,
                            const float* __restrict__ Wxb,
                            const float* __restrict__ bf,
                            const float* __restrict__ bb) {
    const int dir = blockIdx.z;
    const float* __restrict__ W    = dir ? Wxb : Wxf;
    const float* __restrict__ bias = dir ? bb : bf;
    const int n0 = blockIdx.x * 128;
    const int m0 = blockIdx.y * 128;

    __shared__ float As[8][128];   // [k][m]
    __shared__ float Bs[8][128];   // [k][n]

    const int tid = threadIdx.x;           // 0..255
    const int tx = tid & 15;                // col group
    const int ty = tid >> 4;                // row group

    // A-tile load mapping: 128 rows x 8 k = 1024 floats -> one float4/thread
    const int arow = tid >> 1;
    const int acol = (tid & 1) << 2;
    // B-tile load mapping: 8 k x 128 n -> one float4/thread
    const int bk   = tid >> 5;
    const int bcol = (tid & 31) << 2;

    float acc[8][8];
#pragma unroll
    for (int i = 0; i < 8; i++)
#pragma unroll
        for (int j = 0; j < 8; j++) acc[i][j] = 0.0f;

    for (int k0 = 0; k0 < DD; k0 += 8) {
        float4 av = *(const float4*)(X + (size_t)(m0 + arow) * DD + k0 + acol);
        As[acol + 0][arow] = av.x;
        As[acol + 1][arow] = av.y;
        As[acol + 2][arow] = av.z;
        As[acol + 3][arow] = av.w;
        *(float4*)(&Bs[bk][bcol]) =
            *(const float4*)(W + (size_t)(k0 + bk) * GG + n0 + bcol);
        __syncthreads();

#pragma unroll
        for (int kk = 0; kk < 8; kk++) {
            float a[8], b[8];
            *(float4*)(a)     = *(float4*)(&As[kk][ty * 8]);
            *(float4*)(a + 4) = *(float4*)(&As[kk][ty * 8 + 4]);
            *(float4*)(b)     = *(float4*)(&Bs[kk][tx * 8]);
            *(float4*)(b + 4) = *(float4*)(&Bs[kk][tx * 8 + 4]);
#pragma unroll
            for (int i = 0; i < 8; i++)
#pragma unroll
                for (int j = 0; j < 8; j++)
                    acc[i][j] = fmaf(a[i], b[j], acc[i][j]);
        }
        __syncthreads();
    }

    // Epilogue: scatter rows to xz[dir][t][b][*] layout, add bias.
    float bv[8];
#pragma unroll
    for (int j = 0; j < 8; j++) bv[j] = bias[n0 + tx * 8 + j];

#pragma unroll
    for (int i = 0; i < 8; i++) {
        int m  = m0 + ty * 8 + i;
        int bi = m >> 9;        // / T
        int tt = m & (TT - 1);  // % T
        float* dst = g_xz + (((size_t)dir * TT + tt) * BB + bi) * GG + n0 + tx * 8;
#pragma unroll
        for (int j = 0; j < 8; j++) dst[j] = acc[i][j] + bv[j];
    }
}

// ---------------------------------------------------------------------------
// One recurrence step, both directions in one launch.
// grid = (64, 2): blockIdx.x -> 16 hidden units (all 4 gate columns),
// blockIdx.y -> direction. 256 threads, 64x64x1024 fp32 GEMM (4x4/thread),
// fused gate math + state update + output store.
// h double-buffered by parity to avoid cross-CTA read/write race.
// ---------------------------------------------------------------------------
__global__ void step_kernel(int s,
                            const float* __restrict__ Whf,
                            const float* __restrict__ Whb,
                            float* __restrict__ out) {
    const int dir = blockIdx.y;
    const int t = dir ? (TT - 1 - s) : s;
    const float* __restrict__ Wh = dir ? Whb : Whf;
    const int j0 = blockIdx.x * 16;

    const float* __restrict__ hprev = g_h[s & 1] + (size_t)dir * BB * HH;
    float* __restrict__ hnext       = g_h[(s + 1) & 1] + (size_t)dir * BB * HH;
    float* __restrict__ cc          = g_c + (size_t)dir * BB * HH;
    const float* __restrict__ xz    = g_xz + ((size_t)dir * TT + t) * BB * GG;

    __shared__ float As[16][64];    // [k][b]   h tile
    __shared__ float Bs[16][64];    // [k][c]   c = gate*16 + jj
    __shared__ float zt[64][68];    // z tile (padded)

    const int tid = threadIdx.x;    // 0..255
    const int tx = tid & 15;        // 4 cols each
    const int ty = tid >> 4;        // 4 rows each

    float acc[4][4] = {};

    const int lb = tid >> 2;            // batch row for A load
    const int lk = (tid & 3) << 2;      // k quad for A load

    for (int k0 = 0; k0 < HH; k0 += 16) {
        // Load h tile: As[k][b] = hprev[b][k0+k]
        float4 hv = *(const float4*)(hprev + (size_t)lb * HH + k0 + lk);
        As[lk + 0][lb] = hv.x;
        As[lk + 1][lb] = hv.y;
        As[lk + 2][lb] = hv.z;
        As[lk + 3][lb] = hv.w;

        // Load Wh tile: Bs[k][c], column c -> gate*H + j0 + jj
#pragma unroll
        for (int l = 0; l < 4; l++) {
            int idx = l * 256 + tid;
            int k = idx >> 6;
            int c = idx & 63;
            int col = ((c >> 4) << 10) + j0 + (c & 15);
            Bs[k][c] = Wh[(size_t)(k0 + k) * GG + col];
        }
        __syncthreads();

#pragma unroll
        for (int kk = 0; kk < 16; kk++) {
            float a[4], b[4];
            *(float4*)a = *(float4*)(&As[kk][ty * 4]);
            *(float4*)b = *(float4*)(&Bs[kk][tx * 4]);
#pragma unroll
            for (int i = 0; i < 4; i++)
#pragma unroll
                for (int j = 0; j < 4; j++)
                    acc[i][j] = fmaf(a[i], b[j], acc[i][j]);
        }
        __syncthreads();
    }

    // Stash z tile so each thread can gather all 4 gates of a hidden unit.
#pragma unroll
    for (int i = 0; i < 4; i++)
#pragma unroll
        for (int j = 0; j < 4; j++)
            zt[ty * 4 + i][tx * 4 + j] = acc[i][j];
    __syncthreads();

    // Gate math: 64 b x 16 jj = 1024 units, 4 per thread.
    for (int p = tid; p < 1024; p += 256) {
        int b  = p >> 4;
        int jj = p & 15;
        int j  = j0 + jj;
        const float* xzb = xz + (size_t)b * GG;

        float zi = zt[b][jj]      + xzb[j];
        float zf = zt[b][16 + jj] + xzb[HH + j];
        float zo = zt[b][32 + jj] + xzb[2 * HH + j];
        float zg = zt[b][48 + jj] + xzb[3 * HH + j];

        float ig = 1.0f / (1.0f + expf(-zi));
        float fg = 1.0f / (1.0f + expf(-zf));
        float og = 1.0f / (1.0f + expf(-zo));
        float gg = tanhf(zg);

        size_t sidx = (size_t)b * HH + j;
        float cn = fg * cc[sidx] + ig * gg;
        float hn = og * tanhf(cn);

        cc[sidx] = cn;
        hnext[sidx] = hn;
        out[(((size_t)b * TT + t) * 2 + dir) * HH + j] = hn;
    }
}

// ---------------------------------------------------------------------------
// Launch: init -> projection -> 512 sequential step kernels (graph-capturable,
// stream-ordered, no allocations, no syncs).
// ---------------------------------------------------------------------------
extern "C" void kernel_launch(void* const* d_in, const int* in_sizes, int n_in,
                              void* d_out, int out_size) {
    const float* X    = (const float*)d_in[0];
    const float* Wx_f = (const float*)d_in[1];
    const float* Wh_f = (const float*)d_in[2];
    const float* b_f  = (const float*)d_in[3];
    const float* Wx_b = (const float*)d_in[4];
    const float* Wh_b = (const float*)d_in[5];
    const float* b_b  = (const float*)d_in[6];
    float* out = (float*)d_out;

    init_kernel<<<512, 256>>>();

    dim3 pg(GG / 128, (BB * TT) / 128, 2);
    proj_kernel<<<pg, 256>>>(X, Wx_f, Wx_b, b_f, b_b);

    for (int s = 0; s < TT; s++) {
        step_kernel<<<dim3(64, 2), 256>>>(s, Wh_f, Wh_b, out);
    }
}